// round 7
// baseline (speedup 1.0000x reference)
#include <cuda_runtime.h>
#include <cstdint>
#include <math.h>

#define TOPK 8
#define NSPECIAL 999
#define DDIM 768
#define SPLIT 8
#define NT1 128          // kernel-1 block (per-segment top-8)
#define NT2 256          // kernel-2 block (merge + score)
#define MAXPOS 4096

// scratch: per (pos, segment) sorted top-8 candidate lists
__device__ float g_cv[MAXPOS * SPLIT * TOPK];
__device__ int   g_ci[MAXPOS * SPLIT * TOPK];

// jax.lax.top_k ordering: higher value first; ties -> lower index first.
__device__ __forceinline__ bool better(float v1, int i1, float v2, int i2) {
    return (v1 > v2) || (v1 == v2 && i1 < i2);
}

__device__ __forceinline__ void ins8(float v, int i, float lv[TOPK], int li[TOPK]) {
    if (!better(v, i, lv[TOPK - 1], li[TOPK - 1])) return;
    lv[TOPK - 1] = v; li[TOPK - 1] = i;
#pragma unroll
    for (int k = TOPK - 1; k > 0; k--) {
        if (better(lv[k], li[k], lv[k - 1], li[k - 1])) {
            float tv = lv[k]; lv[k] = lv[k - 1]; lv[k - 1] = tv;
            int   ti = li[k]; li[k] = li[k - 1]; li[k - 1] = ti;
        } else break;
    }
}

// ---------------- kernel 1: per-segment exact top-8 ----------------
__global__ __launch_bounds__(NT1)
void topk_seg_kernel(const float* __restrict__ lm,   // [BS, V]
                     const int*   __restrict__ tok,
                     const float* __restrict__ ru,
                     int V, int seg_len)
{
    const int pos = blockIdx.x;
    const int seg = blockIdx.y;
    const int tid = threadIdx.x;

    const int st = tok[pos];
    if (!((st >= NSPECIAL) && (ru[pos] > 0.7f))) return;   // non-swap: no work

    const int start = seg * seg_len;
    const int end   = min(start + seg_len, V);
    if (start >= end) {
        if (tid < TOPK) {
            g_cv[(pos * SPLIT + seg) * TOPK + tid] = -INFINITY;
            g_ci[(pos * SPLIT + seg) * TOPK + tid] = 0x7fffffff;
        }
        return;
    }

    float lv[TOPK]; int li[TOPK];
#pragma unroll
    for (int k = 0; k < TOPK; k++) { lv[k] = -INFINITY; li[k] = 0x7fffffff; }

    // element-index base of this segment within the flat lm array
    const size_t base = (size_t)pos * V + start;
    // peel to 16B (4-element) alignment: V%4==2 makes odd rows 8B-phased
    const int mis   = (int)(base & 3);
    const int peel  = mis ? (4 - mis) : 0;
    const int navail = end - start;
    const int npeel  = min(peel, navail);

    // scalar prologue (<=3 elements, all threads see same small range)
    for (int j = tid; j < npeel; j += NT1) {
        float v = __ldg(lm + base + j);
        if (v > lv[TOPK - 1]) ins8(v, start + j, lv, li);
    }

    // aligned float4 main loop with max4 guard (exact: per-thread indices
    // increase monotonically; equal-value later elements never displace)
    const float4* p4 = (const float4*)(lm + base + npeel);
    const int n4 = (navail - npeel) >> 2;
#pragma unroll 4
    for (int j = tid; j < n4; j += NT1) {
        float4 p = __ldg(p4 + j);
        float m = fmaxf(fmaxf(p.x, p.y), fmaxf(p.z, p.w));
        if (m > lv[TOPK - 1]) {
            int bi = start + npeel + 4 * j;
            ins8(p.x, bi,     lv, li);
            ins8(p.y, bi + 1, lv, li);
            ins8(p.z, bi + 2, lv, li);
            ins8(p.w, bi + 3, lv, li);
        }
    }

    // scalar tail
    for (int j = npeel + (n4 << 2) + tid; j < navail; j += NT1) {
        float v = __ldg(lm + base + j);
        if (v > lv[TOPK - 1]) ins8(v, start + j, lv, li);
    }

    // block merge tree of sorted-8 lists
    __shared__ float sv[NT1 * TOPK];
    __shared__ int   si[NT1 * TOPK];
#pragma unroll
    for (int k = 0; k < TOPK; k++) { sv[tid * TOPK + k] = lv[k]; si[tid * TOPK + k] = li[k]; }
    __syncthreads();

    for (int str = NT1 / 2; str >= 1; str >>= 1) {
        if (tid < str) {
            int ia = tid * TOPK, ib = (tid + str) * TOPK;
            float mv[TOPK]; int mi[TOPK];
#pragma unroll
            for (int k = 0; k < TOPK; k++) {
                float av = sv[ia]; int ai = si[ia];
                float bv = sv[ib]; int bi = si[ib];
                bool ta = better(av, ai, bv, bi);
                mv[k] = ta ? av : bv;
                mi[k] = ta ? ai : bi;
                if (ta) ia++; else ib++;
            }
#pragma unroll
            for (int k = 0; k < TOPK; k++) { sv[tid * TOPK + k] = mv[k]; si[tid * TOPK + k] = mi[k]; }
        }
        __syncthreads();
    }

    if (tid < TOPK) {
        g_cv[(pos * SPLIT + seg) * TOPK + tid] = sv[tid];
        g_ci[(pos * SPLIT + seg) * TOPK + tid] = si[tid];
    }
}

// ---------------- kernel 2: merge segments + score + argmax ----------------
__global__ __launch_bounds__(NT2)
void dvat_final_kernel(const float* __restrict__ dgrad,
                       const float* __restrict__ semb,
                       const float* __restrict__ emb,
                       const int*   __restrict__ tok,
                       const int*   __restrict__ amask,
                       const float* __restrict__ ru,
                       float*       __restrict__ out)
{
    const int pos = blockIdx.x;
    const int tid = threadIdx.x;
    const int st  = tok[pos];

    const bool swap = (st >= NSPECIAL) && (ru[pos] > 0.7f);
    if (!swap) {
        if (tid == 0) out[pos] = (float)st;
        return;
    }

    __shared__ __align__(16) float s_dg[DDIM];
    __shared__ __align__(16) float s_sr[DDIM];
    __shared__ float s_cv[SPLIT * TOPK];
    __shared__ int   s_ci[SPLIT * TOPK];
    __shared__ float t8v[TOPK];
    __shared__ int   t8i[TOPK];
    __shared__ float cscore[TOPK];
    __shared__ int   cidx[TOPK];

    // stage per-position rows + candidates
    {
        const float4* g4 = (const float4*)(dgrad + (size_t)pos * DDIM);
        const float4* s4 = (const float4*)(semb  + (size_t)pos * DDIM);
        float4* sg = (float4*)s_dg;
        float4* ss = (float4*)s_sr;
        for (int j = tid; j < DDIM / 4; j += NT2) { sg[j] = g4[j]; ss[j] = s4[j]; }
    }
    if (tid < SPLIT * TOPK) {
        s_cv[tid] = g_cv[pos * SPLIT * TOPK + tid];
        s_ci[tid] = g_ci[pos * SPLIT * TOPK + tid];
    }
    __syncthreads();

    // single-thread 8-way merge of sorted lists -> global top-8 (exact jax order)
    if (tid == 0) {
        int head[SPLIT];
#pragma unroll
        for (int s = 0; s < SPLIT; s++) head[s] = 0;
#pragma unroll
        for (int k = 0; k < TOPK; k++) {
            float bv = -INFINITY; int bi = 0x7fffffff; int bs = 0;
#pragma unroll
            for (int s = 0; s < SPLIT; s++) {
                int h = head[s];
                float v = s_cv[s * TOPK + h];
                int   i = s_ci[s * TOPK + h];
                if (better(v, i, bv, bi)) { bv = v; bi = i; bs = s; }
            }
            t8v[k] = bv; t8i[k] = bi;
            head[bs] = min(head[bs] + 1, TOPK - 1);
        }
    }
    __syncthreads();

    // one warp per candidate scoring
    const int am   = amask[pos];
    const int wid  = tid >> 5;
    const int lane = tid & 31;

    int v = t8i[wid] * am;
    float score = -INFINITY;
    if (v >= NSPECIAL && v != st) {
        const float4* ev = (const float4*)(emb + (size_t)v * DDIM);
        const float4* g4 = (const float4*)s_dg;
        const float4* s4 = (const float4*)s_sr;
        float gdot = 0.f, sdot = 0.f, vsq = 0.f, pdot = 0.f, ssq = 0.f;
#pragma unroll
        for (int j = lane; j < DDIM / 4; j += 32) {
            float4 e = __ldg(ev + j);
            float4 g = g4[j];
            float4 s = s4[j];
            gdot += e.x * g.x + e.y * g.y + e.z * g.z + e.w * g.w;
            sdot += e.x * s.x + e.y * s.y + e.z * s.z + e.w * s.w;
            vsq  += e.x * e.x + e.y * e.y + e.z * e.z + e.w * e.w;
            pdot += g.x * s.x + g.y * s.y + g.z * s.z + g.w * s.w;
            ssq  += s.x * s.x + s.y * s.y + s.z * s.z + s.w * s.w;
        }
#pragma unroll
        for (int o = 16; o > 0; o >>= 1) {
            gdot += __shfl_down_sync(0xffffffffu, gdot, o);
            sdot += __shfl_down_sync(0xffffffffu, sdot, o);
            vsq  += __shfl_down_sync(0xffffffffu, vsq,  o);
            pdot += __shfl_down_sync(0xffffffffu, pdot, o);
            ssq  += __shfl_down_sync(0xffffffffu, ssq,  o);
        }
        if (lane == 0) {
            float sqn = ssq + vsq - 2.0f * sdot;
            float dn  = sqrtf(fmaxf(sqn, 0.0f) + 1e-20f);
            score = (gdot - pdot) / dn;
        }
    }
    if (lane == 0) { cscore[wid] = score; cidx[wid] = v; }
    __syncthreads();

    if (tid == 0) {
        float best = 0.f; int bi = 0; bool found = false;
#pragma unroll
        for (int k = 0; k < TOPK; k++) {
            float sc = cscore[k]; int vi = cidx[k];
            if (sc != -INFINITY) {
                if (!found || sc > best || (sc == best && vi < bi)) {
                    best = sc; bi = vi; found = true;
                }
            }
        }
        out[pos] = (float)(found ? bi : 0);
    }
}

extern "C" void kernel_launch(void* const* d_in, const int* in_sizes, int n_in,
                              void* d_out, int out_size) {
    // size-pattern-driven input identification (order-robust)
    int idx_lm = 0, idx_emb = 0;
    long sz_lm = -1, sz_emb = -1;
    for (int i = 0; i < n_in; i++) {
        long s = in_sizes[i];
        if (s > sz_lm) { sz_emb = sz_lm; idx_emb = idx_lm; sz_lm = s; idx_lm = i; }
        else if (s > sz_emb) { sz_emb = s; idx_emb = i; }
    }
    int mids[2], nm = 0, smalls[3], ns = 0;
    long sz_small = 0x7fffffff;
    for (int i = 0; i < n_in; i++)
        if (i != idx_lm && i != idx_emb && (long)in_sizes[i] < sz_small) sz_small = in_sizes[i];
    for (int i = 0; i < n_in; i++) {
        if (i == idx_lm || i == idx_emb) continue;
        if ((long)in_sizes[i] == sz_small) { if (ns < 3) smalls[ns++] = i; }
        else                               { if (nm < 2) mids[nm++] = i; }
    }
    int idx_dg = mids[0], idx_se = mids[1];
    int idx_tok, idx_am, idx_ru;
    if (smalls[0] == 0) { idx_am = smalls[0]; idx_ru = smalls[1]; idx_tok = smalls[2]; }
    else                { idx_tok = smalls[0]; idx_am = smalls[1]; idx_ru = smalls[2]; }

    const float* dgrad = (const float*)d_in[idx_dg];
    const float* semb  = (const float*)d_in[idx_se];
    const float* emb   = (const float*)d_in[idx_emb];
    const int*   tok   = (const int*)  d_in[idx_tok];
    const float* lm    = (const float*)d_in[idx_lm];
    const int*   am    = (const int*)  d_in[idx_am];
    const float* ru    = (const float*)d_in[idx_ru];
    float* out = (float*)d_out;

    const int BS = in_sizes[idx_tok];                   // B*S = 2048
    const int V  = (int)((long)in_sizes[idx_lm] / BS);  // 30522
    int seg_len = ((V + SPLIT - 1) / SPLIT + 3) & ~3;   // multiple of 4

    dim3 g1(BS, SPLIT);
    topk_seg_kernel<<<g1, NT1>>>(lm, tok, ru, V, seg_len);
    dvat_final_kernel<<<BS, NT2>>>(dgrad, semb, emb, tok, am, ru, out);
}

// round 8
// speedup vs baseline: 1.3676x; 1.3676x over previous
#include <cuda_runtime.h>
#include <cstdint>
#include <math.h>

#define TOPK 8
#define NSPECIAL 999
#define DDIM 768
#define SPLIT 8
#define NT1 128          // kernel-1 block (per-segment top-8)
#define NT2 256          // kernel-2 block (merge + score)
#define MAXPOS 4096

// scratch: per (pos, segment) sorted top-8 candidate lists
__device__ float g_cv[MAXPOS * SPLIT * TOPK];
__device__ int   g_ci[MAXPOS * SPLIT * TOPK];

// jax.lax.top_k ordering: higher value first; ties -> lower index first.
__device__ __forceinline__ bool better(float v1, int i1, float v2, int i2) {
    return (v1 > v2) || (v1 == v2 && i1 < i2);
}

__device__ __forceinline__ void ins8(float v, int i, float lv[TOPK], int li[TOPK]) {
    if (!better(v, i, lv[TOPK - 1], li[TOPK - 1])) return;
    lv[TOPK - 1] = v; li[TOPK - 1] = i;
#pragma unroll
    for (int k = TOPK - 1; k > 0; k--) {
        if (better(lv[k], li[k], lv[k - 1], li[k - 1])) {
            float tv = lv[k]; lv[k] = lv[k - 1]; lv[k - 1] = tv;
            int   ti = li[k]; li[k] = li[k - 1]; li[k - 1] = ti;
        } else break;
    }
}

// ---------------- kernel 1: per-segment exact top-8 ----------------
__global__ __launch_bounds__(NT1)
void topk_seg_kernel(const float* __restrict__ lm,   // [BS, V]
                     const int*   __restrict__ tok,
                     const float* __restrict__ ru,
                     int V, int seg_len)
{
    const int pos = blockIdx.x;
    const int seg = blockIdx.y;
    const int tid = threadIdx.x;

    const int st = tok[pos];
    if (!((st >= NSPECIAL) && (ru[pos] > 0.7f))) return;   // non-swap: no work

    const int start = seg * seg_len;
    const int end   = min(start + seg_len, V);
    if (start >= end) {
        if (tid < TOPK) {
            g_cv[(pos * SPLIT + seg) * TOPK + tid] = -INFINITY;
            g_ci[(pos * SPLIT + seg) * TOPK + tid] = 0x7fffffff;
        }
        return;
    }

    float lv[TOPK]; int li[TOPK];
#pragma unroll
    for (int k = 0; k < TOPK; k++) { lv[k] = -INFINITY; li[k] = 0x7fffffff; }

    // base is even (V even, seg_len even) -> float2 always 8B-aligned
    const size_t base = (size_t)pos * V + start;
    const int navail = end - start;
    const int n2 = navail >> 1;
    const float2* p2 = (const float2*)(lm + base);

    // main loop: 4 independent float2 loads per round (MLP=4), one guard.
    // Per-thread indices are strictly increasing, so the strict '>' guard is
    // exact under the value-desc/index-asc tie-break.
    int j = tid;
    for (; j + 3 * NT1 < n2; j += 4 * NT1) {
        float2 a = __ldg(p2 + j);
        float2 b = __ldg(p2 + j + NT1);
        float2 c = __ldg(p2 + j + 2 * NT1);
        float2 d = __ldg(p2 + j + 3 * NT1);
        float m = fmaxf(fmaxf(fmaxf(a.x, a.y), fmaxf(b.x, b.y)),
                        fmaxf(fmaxf(c.x, c.y), fmaxf(d.x, d.y)));
        if (m > lv[TOPK - 1]) {
            int i0 = start + 2 * j;
            ins8(a.x, i0,                 lv, li);
            ins8(a.y, i0 + 1,             lv, li);
            int i1 = start + 2 * (j + NT1);
            ins8(b.x, i1,                 lv, li);
            ins8(b.y, i1 + 1,             lv, li);
            int i2 = start + 2 * (j + 2 * NT1);
            ins8(c.x, i2,                 lv, li);
            ins8(c.y, i2 + 1,             lv, li);
            int i3 = start + 2 * (j + 3 * NT1);
            ins8(d.x, i3,                 lv, li);
            ins8(d.y, i3 + 1,             lv, li);
        }
    }
    // remainder float2s
    for (; j < n2; j += NT1) {
        float2 a = __ldg(p2 + j);
        float m = fmaxf(a.x, a.y);
        if (m > lv[TOPK - 1]) {
            int i0 = start + 2 * j;
            ins8(a.x, i0,     lv, li);
            ins8(a.y, i0 + 1, lv, li);
        }
    }
    // odd element (only if navail odd; V=30522 even so normally unused)
    if ((navail & 1) && tid == 0) {
        float v = __ldg(lm + base + navail - 1);
        if (v > lv[TOPK - 1]) ins8(v, start + navail - 1, lv, li);
    }

    // block merge tree of sorted-8 lists
    __shared__ float sv[NT1 * TOPK];
    __shared__ int   si[NT1 * TOPK];
#pragma unroll
    for (int k = 0; k < TOPK; k++) { sv[tid * TOPK + k] = lv[k]; si[tid * TOPK + k] = li[k]; }
    __syncthreads();

    for (int str = NT1 / 2; str >= 1; str >>= 1) {
        if (tid < str) {
            int ia = tid * TOPK, ib = (tid + str) * TOPK;
            float mv[TOPK]; int mi[TOPK];
#pragma unroll
            for (int k = 0; k < TOPK; k++) {
                float av = sv[ia]; int ai = si[ia];
                float bv = sv[ib]; int bi = si[ib];
                bool ta = better(av, ai, bv, bi);
                mv[k] = ta ? av : bv;
                mi[k] = ta ? ai : bi;
                if (ta) ia++; else ib++;
            }
#pragma unroll
            for (int k = 0; k < TOPK; k++) { sv[tid * TOPK + k] = mv[k]; si[tid * TOPK + k] = mi[k]; }
        }
        __syncthreads();
    }

    if (tid < TOPK) {
        g_cv[(pos * SPLIT + seg) * TOPK + tid] = sv[tid];
        g_ci[(pos * SPLIT + seg) * TOPK + tid] = si[tid];
    }
}

// ---------------- kernel 2: merge segments + score + argmax ----------------
__global__ __launch_bounds__(NT2)
void dvat_final_kernel(const float* __restrict__ dgrad,
                       const float* __restrict__ semb,
                       const float* __restrict__ emb,
                       const int*   __restrict__ tok,
                       const int*   __restrict__ amask,
                       const float* __restrict__ ru,
                       float*       __restrict__ out)
{
    const int pos = blockIdx.x;
    const int tid = threadIdx.x;
    const int st  = tok[pos];

    const bool swap = (st >= NSPECIAL) && (ru[pos] > 0.7f);
    if (!swap) {
        if (tid == 0) out[pos] = (float)st;
        return;
    }

    __shared__ __align__(16) float s_dg[DDIM];
    __shared__ __align__(16) float s_sr[DDIM];
    __shared__ float s_cv[SPLIT * TOPK];
    __shared__ int   s_ci[SPLIT * TOPK];
    __shared__ float t8v[TOPK];
    __shared__ int   t8i[TOPK];
    __shared__ float cscore[TOPK];
    __shared__ int   cidx[TOPK];

    {
        const float4* g4 = (const float4*)(dgrad + (size_t)pos * DDIM);
        const float4* s4 = (const float4*)(semb  + (size_t)pos * DDIM);
        float4* sg = (float4*)s_dg;
        float4* ss = (float4*)s_sr;
        for (int j = tid; j < DDIM / 4; j += NT2) { sg[j] = g4[j]; ss[j] = s4[j]; }
    }
    if (tid < SPLIT * TOPK) {
        s_cv[tid] = g_cv[pos * SPLIT * TOPK + tid];
        s_ci[tid] = g_ci[pos * SPLIT * TOPK + tid];
    }
    __syncthreads();

    // single-thread 8-way merge of sorted lists -> global top-8 (exact jax order)
    if (tid == 0) {
        int head[SPLIT];
#pragma unroll
        for (int s = 0; s < SPLIT; s++) head[s] = 0;
#pragma unroll
        for (int k = 0; k < TOPK; k++) {
            float bv = -INFINITY; int bi = 0x7fffffff; int bs = 0;
#pragma unroll
            for (int s = 0; s < SPLIT; s++) {
                int h = head[s];
                float v = s_cv[s * TOPK + h];
                int   i = s_ci[s * TOPK + h];
                if (better(v, i, bv, bi)) { bv = v; bi = i; bs = s; }
            }
            t8v[k] = bv; t8i[k] = bi;
            head[bs] = min(head[bs] + 1, TOPK - 1);
        }
    }
    __syncthreads();

    // one warp per candidate scoring
    const int am   = amask[pos];
    const int wid  = tid >> 5;
    const int lane = tid & 31;

    int v = t8i[wid] * am;
    float score = -INFINITY;
    if (v >= NSPECIAL && v != st) {
        const float4* ev = (const float4*)(emb + (size_t)v * DDIM);
        const float4* g4 = (const float4*)s_dg;
        const float4* s4 = (const float4*)s_sr;
        float gdot = 0.f, sdot = 0.f, vsq = 0.f, pdot = 0.f, ssq = 0.f;
#pragma unroll
        for (int j = lane; j < DDIM / 4; j += 32) {
            float4 e = __ldg(ev + j);
            float4 g = g4[j];
            float4 s = s4[j];
            gdot += e.x * g.x + e.y * g.y + e.z * g.z + e.w * g.w;
            sdot += e.x * s.x + e.y * s.y + e.z * s.z + e.w * s.w;
            vsq  += e.x * e.x + e.y * e.y + e.z * e.z + e.w * e.w;
            pdot += g.x * s.x + g.y * s.y + g.z * s.z + g.w * s.w;
            ssq  += s.x * s.x + s.y * s.y + s.z * s.z + s.w * s.w;
        }
#pragma unroll
        for (int o = 16; o > 0; o >>= 1) {
            gdot += __shfl_down_sync(0xffffffffu, gdot, o);
            sdot += __shfl_down_sync(0xffffffffu, sdot, o);
            vsq  += __shfl_down_sync(0xffffffffu, vsq,  o);
            pdot += __shfl_down_sync(0xffffffffu, pdot, o);
            ssq  += __shfl_down_sync(0xffffffffu, ssq,  o);
        }
        if (lane == 0) {
            float sqn = ssq + vsq - 2.0f * sdot;
            float dn  = sqrtf(fmaxf(sqn, 0.0f) + 1e-20f);
            score = (gdot - pdot) / dn;
        }
    }
    if (lane == 0) { cscore[wid] = score; cidx[wid] = v; }
    __syncthreads();

    if (tid == 0) {
        float best = 0.f; int bi = 0; bool found = false;
#pragma unroll
        for (int k = 0; k < TOPK; k++) {
            float sc = cscore[k]; int vi = cidx[k];
            if (sc != -INFINITY) {
                if (!found || sc > best || (sc == best && vi < bi)) {
                    best = sc; bi = vi; found = true;
                }
            }
        }
        out[pos] = (float)(found ? bi : 0);
    }
}

extern "C" void kernel_launch(void* const* d_in, const int* in_sizes, int n_in,
                              void* d_out, int out_size) {
    // size-pattern-driven input identification (order-robust)
    int idx_lm = 0, idx_emb = 0;
    long sz_lm = -1, sz_emb = -1;
    for (int i = 0; i < n_in; i++) {
        long s = in_sizes[i];
        if (s > sz_lm) { sz_emb = sz_lm; idx_emb = idx_lm; sz_lm = s; idx_lm = i; }
        else if (s > sz_emb) { sz_emb = s; idx_emb = i; }
    }
    int mids[2], nm = 0, smalls[3], ns = 0;
    long sz_small = 0x7fffffff;
    for (int i = 0; i < n_in; i++)
        if (i != idx_lm && i != idx_emb && (long)in_sizes[i] < sz_small) sz_small = in_sizes[i];
    for (int i = 0; i < n_in; i++) {
        if (i == idx_lm || i == idx_emb) continue;
        if ((long)in_sizes[i] == sz_small) { if (ns < 3) smalls[ns++] = i; }
        else                               { if (nm < 2) mids[nm++] = i; }
    }
    int idx_dg = mids[0], idx_se = mids[1];
    int idx_tok, idx_am, idx_ru;
    if (smalls[0] == 0) { idx_am = smalls[0]; idx_ru = smalls[1]; idx_tok = smalls[2]; }
    else                { idx_tok = smalls[0]; idx_am = smalls[1]; idx_ru = smalls[2]; }

    const float* dgrad = (const float*)d_in[idx_dg];
    const float* semb  = (const float*)d_in[idx_se];
    const float* emb   = (const float*)d_in[idx_emb];
    const int*   tok   = (const int*)  d_in[idx_tok];
    const float* lm    = (const float*)d_in[idx_lm];
    const int*   am    = (const int*)  d_in[idx_am];
    const float* ru    = (const float*)d_in[idx_ru];
    float* out = (float*)d_out;

    const int BS = in_sizes[idx_tok];                   // B*S = 2048
    const int V  = (int)((long)in_sizes[idx_lm] / BS);  // 30522
    int seg_len = ((V + SPLIT - 1) / SPLIT + 1) & ~1;   // multiple of 2

    dim3 g1(BS, SPLIT);
    topk_seg_kernel<<<g1, NT1>>>(lm, tok, ru, V, seg_len);
    dvat_final_kernel<<<BS, NT2>>>(dgrad, semb, emb, tok, am, ru, out);
}

// round 9
// speedup vs baseline: 3.1843x; 2.3285x over previous
#include <cuda_runtime.h>
#include <cstdint>
#include <math.h>

#define TOPK 8
#define NSPECIAL 999
#define DDIM 768
#define SPLIT 8
#define NT1 128          // kernel-1 block (per-segment top-8)
#define NT2 256          // kernel-2 block (merge + score)
#define MAXPOS 4096
#define V2PT 16          // float2 regs per thread: covers seg_len <= 4096
#define CANDMAX 3840     // >= max navail per segment (exact-safe capacity)

// scratch: per (pos, segment) sorted top-8 candidate lists
__device__ float g_cv[MAXPOS * SPLIT * TOPK];
__device__ int   g_ci[MAXPOS * SPLIT * TOPK];

// jax.lax.top_k ordering: higher value first; ties -> lower index first.
__device__ __forceinline__ bool better(float v1, int i1, float v2, int i2) {
    return (v1 > v2) || (v1 == v2 && i1 < i2);
}

__device__ __forceinline__ void ins8(float v, int i, float lv[TOPK], int li[TOPK]) {
    if (!better(v, i, lv[TOPK - 1], li[TOPK - 1])) return;
    lv[TOPK - 1] = v; li[TOPK - 1] = i;
#pragma unroll
    for (int k = TOPK - 1; k > 0; k--) {
        if (better(lv[k], li[k], lv[k - 1], li[k - 1])) {
            float tv = lv[k]; lv[k] = lv[k - 1]; lv[k - 1] = tv;
            int   ti = li[k]; li[k] = li[k - 1]; li[k - 1] = ti;
        } else break;
    }
}

// value-only sorted-8 insert (for the threshold over thread maxes)
__device__ __forceinline__ void ins8v(float v, float lv[TOPK]) {
    if (v <= lv[TOPK - 1]) return;
    lv[TOPK - 1] = v;
#pragma unroll
    for (int k = TOPK - 1; k > 0; k--) {
        if (lv[k] > lv[k - 1]) { float t = lv[k]; lv[k] = lv[k - 1]; lv[k - 1] = t; }
        else break;
    }
}

// ---------------- kernel 1: per-segment exact top-8 (2-pass threshold) ----------------
__global__ __launch_bounds__(NT1)
void topk_seg_kernel(const float* __restrict__ lm,   // [BS, V]
                     const int*   __restrict__ tok,
                     const float* __restrict__ ru,
                     int V, int seg_len)
{
    const int pos = blockIdx.x;
    const int seg = blockIdx.y;
    const int tid = threadIdx.x;

    const int st = tok[pos];
    if (!((st >= NSPECIAL) && (ru[pos] > 0.7f))) return;   // non-swap: no work

    const int start = seg * seg_len;
    const int end   = min(start + seg_len, V);
    const int navail = end - start;
    if (navail <= 0) {
        if (tid < TOPK) {
            g_cv[(pos * SPLIT + seg) * TOPK + tid] = -INFINITY;
            g_ci[(pos * SPLIT + seg) * TOPK + tid] = 0x7fffffff;
        }
        return;
    }

    __shared__ float s_max[NT1];
    __shared__ float s_cv[CANDMAX];
    __shared__ int   s_ci[CANDMAX];
    __shared__ float s_thr;
    __shared__ int   s_cnt;

    // ---- pass 1: branchless register-resident load + per-thread max ----
    const size_t base = (size_t)pos * V + start;   // even (V even, seg_len even)
    const float2* p2 = (const float2*)(lm + base);
    const int n2 = navail >> 1;

    float2 vals[V2PT];
#pragma unroll
    for (int k = 0; k < V2PT; k++) {
        int j = tid + k * NT1;
        vals[k] = (j < n2) ? __ldg(p2 + j) : make_float2(-INFINITY, -INFINITY);
    }
    float extra = -INFINITY;
    if ((navail & 1) && tid == 0) extra = __ldg(lm + base + navail - 1);

    float tmax = extra;
#pragma unroll
    for (int k = 0; k < V2PT; k++)
        tmax = fmaxf(tmax, fmaxf(vals[k].x, vals[k].y));

    s_max[tid] = tmax;
    __syncthreads();

    // ---- threshold: 8th-largest of the 128 thread maxes (valid lower bound
    //      on the true 8th-largest value of the segment) ----
    if (tid == 0) {
        float t8[TOPK];
#pragma unroll
        for (int k = 0; k < TOPK; k++) t8[k] = -INFINITY;
        for (int i = 0; i < NT1; i++) ins8v(s_max[i], t8);
        s_thr = t8[TOPK - 1];
        s_cnt = 0;
    }
    __syncthreads();
    const float t = s_thr;

    // ---- pass 2: compact candidates >= t from registers (rare pushes) ----
#pragma unroll
    for (int k = 0; k < V2PT; k++) {
        int j = tid + k * NT1;
        if (j < n2) {
            if (vals[k].x >= t) {
                int s = atomicAdd(&s_cnt, 1);
                s_cv[s] = vals[k].x; s_ci[s] = start + 2 * j;
            }
            if (vals[k].y >= t) {
                int s = atomicAdd(&s_cnt, 1);
                s_cv[s] = vals[k].y; s_ci[s] = start + 2 * j + 1;
            }
        }
    }
    if (extra >= t) {   // only thread 0 can have finite extra
        int s = atomicAdd(&s_cnt, 1);
        s_cv[s] = extra; s_ci[s] = start + navail - 1;
    }
    __syncthreads();

    // ---- exact jax top-8 (value desc, index asc) over the c candidates ----
    if (tid == 0) {
        float lv[TOPK]; int li[TOPK];
#pragma unroll
        for (int k = 0; k < TOPK; k++) { lv[k] = -INFINITY; li[k] = 0x7fffffff; }
        const int c = s_cnt;
        for (int i = 0; i < c; i++) ins8(s_cv[i], s_ci[i], lv, li);
        float* ov = g_cv + (pos * SPLIT + seg) * TOPK;
        int*   oi = g_ci + (pos * SPLIT + seg) * TOPK;
#pragma unroll
        for (int k = 0; k < TOPK; k++) { ov[k] = lv[k]; oi[k] = li[k]; }
    }
}

// ---------------- kernel 2: merge segments + score + argmax ----------------
__global__ __launch_bounds__(NT2)
void dvat_final_kernel(const float* __restrict__ dgrad,
                       const float* __restrict__ semb,
                       const float* __restrict__ emb,
                       const int*   __restrict__ tok,
                       const int*   __restrict__ amask,
                       const float* __restrict__ ru,
                       float*       __restrict__ out)
{
    const int pos = blockIdx.x;
    const int tid = threadIdx.x;
    const int st  = tok[pos];

    const bool swap = (st >= NSPECIAL) && (ru[pos] > 0.7f);
    if (!swap) {
        if (tid == 0) out[pos] = (float)st;
        return;
    }

    __shared__ __align__(16) float s_dg[DDIM];
    __shared__ __align__(16) float s_sr[DDIM];
    __shared__ float s_cv[SPLIT * TOPK];
    __shared__ int   s_ci[SPLIT * TOPK];
    __shared__ float t8v[TOPK];
    __shared__ int   t8i[TOPK];
    __shared__ float cscore[TOPK];
    __shared__ int   cidx[TOPK];

    {
        const float4* g4 = (const float4*)(dgrad + (size_t)pos * DDIM);
        const float4* s4 = (const float4*)(semb  + (size_t)pos * DDIM);
        float4* sg = (float4*)s_dg;
        float4* ss = (float4*)s_sr;
        for (int j = tid; j < DDIM / 4; j += NT2) { sg[j] = g4[j]; ss[j] = s4[j]; }
    }
    if (tid < SPLIT * TOPK) {
        s_cv[tid] = g_cv[pos * SPLIT * TOPK + tid];
        s_ci[tid] = g_ci[pos * SPLIT * TOPK + tid];
    }
    __syncthreads();

    // single-thread 8-way merge of sorted lists -> global top-8 (exact jax order)
    if (tid == 0) {
        int head[SPLIT];
#pragma unroll
        for (int s = 0; s < SPLIT; s++) head[s] = 0;
#pragma unroll
        for (int k = 0; k < TOPK; k++) {
            float bv = -INFINITY; int bi = 0x7fffffff; int bs = 0;
#pragma unroll
            for (int s = 0; s < SPLIT; s++) {
                int h = head[s];
                float v = s_cv[s * TOPK + h];
                int   i = s_ci[s * TOPK + h];
                if (better(v, i, bv, bi)) { bv = v; bi = i; bs = s; }
            }
            t8v[k] = bv; t8i[k] = bi;
            head[bs] = min(head[bs] + 1, TOPK - 1);
        }
    }
    __syncthreads();

    // one warp per candidate scoring
    const int am   = amask[pos];
    const int wid  = tid >> 5;
    const int lane = tid & 31;

    int v = t8i[wid] * am;
    float score = -INFINITY;
    if (v >= NSPECIAL && v != st) {
        const float4* ev = (const float4*)(emb + (size_t)v * DDIM);
        const float4* g4 = (const float4*)s_dg;
        const float4* s4 = (const float4*)s_sr;
        float gdot = 0.f, sdot = 0.f, vsq = 0.f, pdot = 0.f, ssq = 0.f;
#pragma unroll
        for (int j = lane; j < DDIM / 4; j += 32) {
            float4 e = __ldg(ev + j);
            float4 g = g4[j];
            float4 s = s4[j];
            gdot += e.x * g.x + e.y * g.y + e.z * g.z + e.w * g.w;
            sdot += e.x * s.x + e.y * s.y + e.z * s.z + e.w * s.w;
            vsq  += e.x * e.x + e.y * e.y + e.z * e.z + e.w * e.w;
            pdot += g.x * s.x + g.y * s.y + g.z * s.z + g.w * s.w;
            ssq  += s.x * s.x + s.y * s.y + s.z * s.z + s.w * s.w;
        }
#pragma unroll
        for (int o = 16; o > 0; o >>= 1) {
            gdot += __shfl_down_sync(0xffffffffu, gdot, o);
            sdot += __shfl_down_sync(0xffffffffu, sdot, o);
            vsq  += __shfl_down_sync(0xffffffffu, vsq,  o);
            pdot += __shfl_down_sync(0xffffffffu, pdot, o);
            ssq  += __shfl_down_sync(0xffffffffu, ssq,  o);
        }
        if (lane == 0) {
            float sqn = ssq + vsq - 2.0f * sdot;
            float dn  = sqrtf(fmaxf(sqn, 0.0f) + 1e-20f);
            score = (gdot - pdot) / dn;
        }
    }
    if (lane == 0) { cscore[wid] = score; cidx[wid] = v; }
    __syncthreads();

    if (tid == 0) {
        float best = 0.f; int bi = 0; bool found = false;
#pragma unroll
        for (int k = 0; k < TOPK; k++) {
            float sc = cscore[k]; int vi = cidx[k];
            if (sc != -INFINITY) {
                if (!found || sc > best || (sc == best && vi < bi)) {
                    best = sc; bi = vi; found = true;
                }
            }
        }
        out[pos] = (float)(found ? bi : 0);
    }
}

extern "C" void kernel_launch(void* const* d_in, const int* in_sizes, int n_in,
                              void* d_out, int out_size) {
    // size-pattern-driven input identification (order-robust)
    int idx_lm = 0, idx_emb = 0;
    long sz_lm = -1, sz_emb = -1;
    for (int i = 0; i < n_in; i++) {
        long s = in_sizes[i];
        if (s > sz_lm) { sz_emb = sz_lm; idx_emb = idx_lm; sz_lm = s; idx_lm = i; }
        else if (s > sz_emb) { sz_emb = s; idx_emb = i; }
    }
    int mids[2], nm = 0, smalls[3], ns = 0;
    long sz_small = 0x7fffffff;
    for (int i = 0; i < n_in; i++)
        if (i != idx_lm && i != idx_emb && (long)in_sizes[i] < sz_small) sz_small = in_sizes[i];
    for (int i = 0; i < n_in; i++) {
        if (i == idx_lm || i == idx_emb) continue;
        if ((long)in_sizes[i] == sz_small) { if (ns < 3) smalls[ns++] = i; }
        else                               { if (nm < 2) mids[nm++] = i; }
    }
    int idx_dg = mids[0], idx_se = mids[1];
    int idx_tok, idx_am, idx_ru;
    if (smalls[0] == 0) { idx_am = smalls[0]; idx_ru = smalls[1]; idx_tok = smalls[2]; }
    else                { idx_tok = smalls[0]; idx_am = smalls[1]; idx_ru = smalls[2]; }

    const float* dgrad = (const float*)d_in[idx_dg];
    const float* semb  = (const float*)d_in[idx_se];
    const float* emb   = (const float*)d_in[idx_emb];
    const int*   tok   = (const int*)  d_in[idx_tok];
    const float* lm    = (const float*)d_in[idx_lm];
    const int*   am    = (const int*)  d_in[idx_am];
    const float* ru    = (const float*)d_in[idx_ru];
    float* out = (float*)d_out;

    const int BS = in_sizes[idx_tok];                   // B*S = 2048
    const int V  = (int)((long)in_sizes[idx_lm] / BS);  // 30522
    int seg_len = ((V + SPLIT - 1) / SPLIT + 1) & ~1;   // even; 3816 for V=30522

    dim3 g1(BS, SPLIT);
    topk_seg_kernel<<<g1, NT1>>>(lm, tok, ru, V, seg_len);
    dvat_final_kernel<<<BS, NT2>>>(dgrad, semb, emb, tok, am, ru, out);
}

// round 14
// speedup vs baseline: 4.1083x; 1.2902x over previous
#include <cuda_runtime.h>
#include <cstdint>
#include <math.h>

#define TOPK 8
#define NSPECIAL 999
#define DDIM 768
#define SPLIT 16
#define NT1 128          // kernel-1 block (per-segment top-8)
#define NT2 256          // kernel-2 block (merge + score)
#define MAXPOS 4096
#define V2PT 8           // float2 regs per thread: covers seg_len <= 2048
#define CAP 512          // smem candidate capacity (overflow -> exact fallback)

// scratch: per (pos, segment) sorted top-8 candidate lists
__device__ float g_cv[MAXPOS * SPLIT * TOPK];
__device__ int   g_ci[MAXPOS * SPLIT * TOPK];

// jax.lax.top_k ordering: higher value first; ties -> lower index first.
__device__ __forceinline__ bool better(float v1, int i1, float v2, int i2) {
    return (v1 > v2) || (v1 == v2 && i1 < i2);
}

__device__ __forceinline__ void ins8(float v, int i, float lv[TOPK], int li[TOPK]) {
    if (!better(v, i, lv[TOPK - 1], li[TOPK - 1])) return;
    lv[TOPK - 1] = v; li[TOPK - 1] = i;
#pragma unroll
    for (int k = TOPK - 1; k > 0; k--) {
        if (better(lv[k], li[k], lv[k - 1], li[k - 1])) {
            float tv = lv[k]; lv[k] = lv[k - 1]; lv[k - 1] = tv;
            int   ti = li[k]; li[k] = li[k - 1]; li[k - 1] = ti;
        } else break;
    }
}

// ---------------- kernel 1: per-segment exact top-8 (2-pass threshold) ----------------
__global__ __launch_bounds__(NT1)
void topk_seg_kernel(const float* __restrict__ lm,   // [BS, V]
                     const int*   __restrict__ tok,
                     const float* __restrict__ ru,
                     int V, int seg_len)
{
    const int pos = blockIdx.x;
    const int seg = blockIdx.y;
    const int tid = threadIdx.x;

    const int st = tok[pos];
    if (!((st >= NSPECIAL) && (ru[pos] > 0.7f))) return;   // non-swap: no work

    const int start = seg * seg_len;
    const int end   = min(start + seg_len, V);
    const int navail = end - start;
    if (navail <= 0) {
        if (tid < TOPK) {
            g_cv[(pos * SPLIT + seg) * TOPK + tid] = -INFINITY;
            g_ci[(pos * SPLIT + seg) * TOPK + tid] = 0x7fffffff;
        }
        return;
    }

    __shared__ float s_gmax[NT1 / 16];   // 8 group maxes
    __shared__ float s_cv[CAP];
    __shared__ int   s_ci[CAP];
    __shared__ float s_thr;
    __shared__ int   s_cnt;

    // ---- pass 1: branchless register-resident load + per-thread max ----
    const size_t base = (size_t)pos * V + start;   // even (V even, seg_len even)
    const float2* p2 = (const float2*)(lm + base);
    const int n2 = navail >> 1;

    float2 vals[V2PT];
#pragma unroll
    for (int k = 0; k < V2PT; k++) {
        int j = tid + k * NT1;
        vals[k] = (j < n2) ? __ldg(p2 + j) : make_float2(-INFINITY, -INFINITY);
    }
    float extra = -INFINITY;
    if ((navail & 1) && tid == 0) extra = __ldg(lm + base + navail - 1);

    float tmax = extra;
#pragma unroll
    for (int k = 0; k < V2PT; k++)
        tmax = fmaxf(tmax, fmaxf(vals[k].x, vals[k].y));

    // ---- threshold: min of 8 group-of-16 maxes (valid: 8 distinct elements
    //      >= t  =>  true 8th-largest >= t  =>  all true top-8 values >= t) ----
    float gm = tmax;
#pragma unroll
    for (int o = 8; o > 0; o >>= 1)
        gm = fmaxf(gm, __shfl_down_sync(0xffffffffu, gm, o, 16));
    if ((tid & 15) == 0) s_gmax[tid >> 4] = gm;
    if (tid == 0) s_cnt = 0;
    __syncthreads();
    if (tid == 0) {
        float t = s_gmax[0];
#pragma unroll
        for (int g = 1; g < NT1 / 16; g++) t = fminf(t, s_gmax[g]);
        s_thr = t;
    }
    __syncthreads();
    const float t = s_thr;

    // ---- pass 2: compact candidates >= t from registers (rare pushes) ----
#pragma unroll
    for (int k = 0; k < V2PT; k++) {
        int j = tid + k * NT1;
        if (j < n2) {
            if (vals[k].x >= t) {
                int s = atomicAdd(&s_cnt, 1);
                if (s < CAP) { s_cv[s] = vals[k].x; s_ci[s] = start + 2 * j; }
            }
            if (vals[k].y >= t) {
                int s = atomicAdd(&s_cnt, 1);
                if (s < CAP) { s_cv[s] = vals[k].y; s_ci[s] = start + 2 * j + 1; }
            }
        }
    }
    if (extra >= t) {   // only thread 0 can have finite extra
        int s = atomicAdd(&s_cnt, 1);
        if (s < CAP) { s_cv[s] = extra; s_ci[s] = start + navail - 1; }
    }
    __syncthreads();

    // ---- exact jax top-8 (value desc, index asc) over the candidates ----
    if (tid == 0) {
        float lv[TOPK]; int li[TOPK];
#pragma unroll
        for (int k = 0; k < TOPK; k++) { lv[k] = -INFINITY; li[k] = 0x7fffffff; }
        const int c = s_cnt;
        if (c <= CAP) {
            for (int i = 0; i < c; i++) ins8(s_cv[i], s_ci[i], lv, li);
        } else {
            // exact fallback (overflow; unreachable for finite random data):
            // serial rescan of the segment in index order
            for (int i = 0; i < navail; i++) {
                float v = __ldg(lm + base + i);
                if (v >= t) ins8(v, start + i, lv, li);
            }
        }
        float* ov = g_cv + (pos * SPLIT + seg) * TOPK;
        int*   oi = g_ci + (pos * SPLIT + seg) * TOPK;
#pragma unroll
        for (int k = 0; k < TOPK; k++) { ov[k] = lv[k]; oi[k] = li[k]; }
    }
}

// ---------------- kernel 2: merge segments + score + argmax ----------------
__global__ __launch_bounds__(NT2)
void dvat_final_kernel(const float* __restrict__ dgrad,
                       const float* __restrict__ semb,
                       const float* __restrict__ emb,
                       const int*   __restrict__ tok,
                       const int*   __restrict__ amask,
                       const float* __restrict__ ru,
                       float*       __restrict__ out)
{
    const int pos = blockIdx.x;
    const int tid = threadIdx.x;
    const int st  = tok[pos];

    const bool swap = (st >= NSPECIAL) && (ru[pos] > 0.7f);
    if (!swap) {
        if (tid == 0) out[pos] = (float)st;
        return;
    }

    __shared__ __align__(16) float s_dg[DDIM];
    __shared__ __align__(16) float s_sr[DDIM];
    __shared__ float s_cv[SPLIT * TOPK];
    __shared__ int   s_ci[SPLIT * TOPK];
    __shared__ float t8v[TOPK];
    __shared__ int   t8i[TOPK];
    __shared__ float cscore[TOPK];
    __shared__ int   cidx[TOPK];

    {
        const float4* g4 = (const float4*)(dgrad + (size_t)pos * DDIM);
        const float4* s4 = (const float4*)(semb  + (size_t)pos * DDIM);
        float4* sg = (float4*)s_dg;
        float4* ss = (float4*)s_sr;
        for (int j = tid; j < DDIM / 4; j += NT2) { sg[j] = g4[j]; ss[j] = s4[j]; }
    }
    if (tid < SPLIT * TOPK) {
        s_cv[tid] = g_cv[pos * SPLIT * TOPK + tid];
        s_ci[tid] = g_ci[pos * SPLIT * TOPK + tid];
    }
    __syncthreads();

    // single-thread 16-way merge of sorted lists -> global top-8 (exact jax order)
    if (tid == 0) {
        int head[SPLIT];
#pragma unroll
        for (int s = 0; s < SPLIT; s++) head[s] = 0;
#pragma unroll
        for (int k = 0; k < TOPK; k++) {
            float bv = -INFINITY; int bi = 0x7fffffff; int bs = 0;
#pragma unroll
            for (int s = 0; s < SPLIT; s++) {
                int h = head[s];
                float v = s_cv[s * TOPK + h];
                int   i = s_ci[s * TOPK + h];
                if (better(v, i, bv, bi)) { bv = v; bi = i; bs = s; }
            }
            t8v[k] = bv; t8i[k] = bi;
            head[bs] = min(head[bs] + 1, TOPK - 1);
        }
    }
    __syncthreads();

    // one warp per candidate scoring
    const int am   = amask[pos];
    const int wid  = tid >> 5;
    const int lane = tid & 31;

    int v = t8i[wid] * am;
    float score = -INFINITY;
    if (v >= NSPECIAL && v != st) {
        const float4* ev = (const float4*)(emb + (size_t)v * DDIM);
        const float4* g4 = (const float4*)s_dg;
        const float4* s4 = (const float4*)s_sr;
        float gdot = 0.f, sdot = 0.f, vsq = 0.f, pdot = 0.f, ssq = 0.f;
#pragma unroll
        for (int j = lane; j < DDIM / 4; j += 32) {
            float4 e = __ldg(ev + j);
            float4 g = g4[j];
            float4 s = s4[j];
            gdot += e.x * g.x + e.y * g.y + e.z * g.z + e.w * g.w;
            sdot += e.x * s.x + e.y * s.y + e.z * s.z + e.w * s.w;
            vsq  += e.x * e.x + e.y * e.y + e.z * e.z + e.w * e.w;
            pdot += g.x * s.x + g.y * s.y + g.z * s.z + g.w * s.w;
            ssq  += s.x * s.x + s.y * s.y + s.z * s.z + s.w * s.w;
        }
#pragma unroll
        for (int o = 16; o > 0; o >>= 1) {
            gdot += __shfl_down_sync(0xffffffffu, gdot, o);
            sdot += __shfl_down_sync(0xffffffffu, sdot, o);
            vsq  += __shfl_down_sync(0xffffffffu, vsq,  o);
            pdot += __shfl_down_sync(0xffffffffu, pdot, o);
            ssq  += __shfl_down_sync(0xffffffffu, ssq,  o);
        }
        if (lane == 0) {
            float sqn = ssq + vsq - 2.0f * sdot;
            float dn  = sqrtf(fmaxf(sqn, 0.0f) + 1e-20f);
            score = (gdot - pdot) / dn;
        }
    }
    if (lane == 0) { cscore[wid] = score; cidx[wid] = v; }
    __syncthreads();

    if (tid == 0) {
        float best = 0.f; int bi = 0; bool found = false;
#pragma unroll
        for (int k = 0; k < TOPK; k++) {
            float sc = cscore[k]; int vi = cidx[k];
            if (sc != -INFINITY) {
                if (!found || sc > best || (sc == best && vi < bi)) {
                    best = sc; bi = vi; found = true;
                }
            }
        }
        out[pos] = (float)(found ? bi : 0);
    }
}

extern "C" void kernel_launch(void* const* d_in, const int* in_sizes, int n_in,
                              void* d_out, int out_size) {
    // size-pattern-driven input identification (order-robust)
    int idx_lm = 0, idx_emb = 0;
    long sz_lm = -1, sz_emb = -1;
    for (int i = 0; i < n_in; i++) {
        long s = in_sizes[i];
        if (s > sz_lm) { sz_emb = sz_lm; idx_emb = idx_lm; sz_lm = s; idx_lm = i; }
        else if (s > sz_emb) { sz_emb = s; idx_emb = i; }
    }
    int mids[2], nm = 0, smalls[3], ns = 0;
    long sz_small = 0x7fffffff;
    for (int i = 0; i < n_in; i++)
        if (i != idx_lm && i != idx_emb && (long)in_sizes[i] < sz_small) sz_small = in_sizes[i];
    for (int i = 0; i < n_in; i++) {
        if (i == idx_lm || i == idx_emb) continue;
        if ((long)in_sizes[i] == sz_small) { if (ns < 3) smalls[ns++] = i; }
        else                               { if (nm < 2) mids[nm++] = i; }
    }
    int idx_dg = mids[0], idx_se = mids[1];
    int idx_tok, idx_am, idx_ru;
    if (smalls[0] == 0) { idx_am = smalls[0]; idx_ru = smalls[1]; idx_tok = smalls[2]; }
    else                { idx_tok = smalls[0]; idx_am = smalls[1]; idx_ru = smalls[2]; }

    const float* dgrad = (const float*)d_in[idx_dg];
    const float* semb  = (const float*)d_in[idx_se];
    const float* emb   = (const float*)d_in[idx_emb];
    const int*   tok   = (const int*)  d_in[idx_tok];
    const float* lm    = (const float*)d_in[idx_lm];
    const int*   am    = (const int*)  d_in[idx_am];
    const float* ru    = (const float*)d_in[idx_ru];
    float* out = (float*)d_out;

    const int BS = in_sizes[idx_tok];                   // B*S = 2048
    const int V  = (int)((long)in_sizes[idx_lm] / BS);  // 30522
    int seg_len = ((V + SPLIT - 1) / SPLIT + 1) & ~1;   // even; 1908 for V=30522

    dim3 g1(BS, SPLIT);
    topk_seg_kernel<<<g1, NT1>>>(lm, tok, ru, V, seg_len);
    dvat_final_kernel<<<BS, NT2>>>(dgrad, semb, emb, tok, am, ru, out);
}

// round 15
// speedup vs baseline: 4.4744x; 1.0891x over previous
#include <cuda_runtime.h>
#include <cstdint>
#include <math.h>

#define TOPK 8
#define NSPECIAL 999
#define DDIM 768
#define SPLIT 16
#define NT0 1024         // kernel-0 single-block compaction
#define NT1 128          // kernel-1 block (per-segment top-8)
#define NT2 256          // kernel-2 block (merge + score)
#define MAXPOS 4096
#define V2PT 8           // float2 regs per thread: covers seg_len <= 2048
#define CAP 512          // smem candidate capacity (overflow -> exact fallback)

// scratch
__device__ float g_cv[MAXPOS * SPLIT * TOPK];
__device__ int   g_ci[MAXPOS * SPLIT * TOPK];
__device__ int   g_wl[MAXPOS];   // compacted heavy (swap) positions
__device__ int   g_cnt;          // number of heavy positions

// jax.lax.top_k ordering: higher value first; ties -> lower index first.
__device__ __forceinline__ bool better(float v1, int i1, float v2, int i2) {
    return (v1 > v2) || (v1 == v2 && i1 < i2);
}

__device__ __forceinline__ void ins8(float v, int i, float lv[TOPK], int li[TOPK]) {
    if (!better(v, i, lv[TOPK - 1], li[TOPK - 1])) return;
    lv[TOPK - 1] = v; li[TOPK - 1] = i;
#pragma unroll
    for (int k = TOPK - 1; k > 0; k--) {
        if (better(lv[k], li[k], lv[k - 1], li[k - 1])) {
            float tv = lv[k]; lv[k] = lv[k - 1]; lv[k - 1] = tv;
            int   ti = li[k]; li[k] = li[k - 1]; li[k - 1] = ti;
        } else break;
    }
}

// ---------------- kernel 0: swap mask, non-swap writeout, worklist compaction ----------------
__global__ __launch_bounds__(NT0)
void swap_compact_kernel(const int*   __restrict__ tok,
                         const float* __restrict__ ru,
                         float*       __restrict__ out,
                         int BS)
{
    __shared__ int s_cnt;
    const int tid = threadIdx.x;
    if (tid == 0) s_cnt = 0;
    __syncthreads();

    for (int i = tid; i < BS; i += NT0) {
        int   st = tok[i];     // independent loads, issued in parallel
        float r  = ru[i];
        bool swap = (st >= NSPECIAL) && (r > 0.7f);
        if (swap) {
            int s = atomicAdd(&s_cnt, 1);
            g_wl[s] = i;
        } else {
            out[i] = (float)st;
        }
    }
    __syncthreads();
    if (tid == 0) g_cnt = s_cnt;
}

// ---------------- kernel 1: per-heavy-position per-segment exact top-8 ----------------
__global__ __launch_bounds__(NT1)
void topk_seg_kernel(const float* __restrict__ lm,   // [BS, V]
                     int V, int seg_len)
{
    const int widx = blockIdx.x;
    const int cnt  = g_cnt;           // L2-broadcast
    if (widx >= cnt) return;          // dense front: heavies occupy slots first
    const int pos  = g_wl[widx];
    const int seg  = blockIdx.y;
    const int tid  = threadIdx.x;

    const int start = seg * seg_len;
    const int end   = min(start + seg_len, V);
    const int navail = end - start;
    if (navail <= 0) {
        if (tid < TOPK) {
            g_cv[(pos * SPLIT + seg) * TOPK + tid] = -INFINITY;
            g_ci[(pos * SPLIT + seg) * TOPK + tid] = 0x7fffffff;
        }
        return;
    }

    __shared__ float s_gmax[NT1 / 16];   // 8 group maxes
    __shared__ float s_cv[CAP];
    __shared__ int   s_ci[CAP];
    __shared__ float s_thr;
    __shared__ int   s_cnt;

    // ---- pass 1: branchless register-resident load + per-thread max ----
    const size_t base = (size_t)pos * V + start;   // even (V even, seg_len even)
    const float2* p2 = (const float2*)(lm + base);
    const int n2 = navail >> 1;

    float2 vals[V2PT];
#pragma unroll
    for (int k = 0; k < V2PT; k++) {
        int j = tid + k * NT1;
        vals[k] = (j < n2) ? __ldg(p2 + j) : make_float2(-INFINITY, -INFINITY);
    }
    float extra = -INFINITY;
    if ((navail & 1) && tid == 0) extra = __ldg(lm + base + navail - 1);

    float tmax = extra;
#pragma unroll
    for (int k = 0; k < V2PT; k++)
        tmax = fmaxf(tmax, fmaxf(vals[k].x, vals[k].y));

    // ---- threshold: min of 8 group-of-16 maxes (valid: 8 distinct elements
    //      >= t  =>  true 8th-largest >= t  =>  all true top-8 values >= t) ----
    float gm = tmax;
#pragma unroll
    for (int o = 8; o > 0; o >>= 1)
        gm = fmaxf(gm, __shfl_down_sync(0xffffffffu, gm, o, 16));
    if ((tid & 15) == 0) s_gmax[tid >> 4] = gm;
    if (tid == 0) s_cnt = 0;
    __syncthreads();
    if (tid == 0) {
        float t = s_gmax[0];
#pragma unroll
        for (int g = 1; g < NT1 / 16; g++) t = fminf(t, s_gmax[g]);
        s_thr = t;
    }
    __syncthreads();
    const float t = s_thr;

    // ---- pass 2: compact candidates >= t from registers (rare pushes) ----
#pragma unroll
    for (int k = 0; k < V2PT; k++) {
        int j = tid + k * NT1;
        if (j < n2) {
            if (vals[k].x >= t) {
                int s = atomicAdd(&s_cnt, 1);
                if (s < CAP) { s_cv[s] = vals[k].x; s_ci[s] = start + 2 * j; }
            }
            if (vals[k].y >= t) {
                int s = atomicAdd(&s_cnt, 1);
                if (s < CAP) { s_cv[s] = vals[k].y; s_ci[s] = start + 2 * j + 1; }
            }
        }
    }
    if (extra >= t) {
        int s = atomicAdd(&s_cnt, 1);
        if (s < CAP) { s_cv[s] = extra; s_ci[s] = start + navail - 1; }
    }
    __syncthreads();

    // ---- exact jax top-8 (value desc, index asc) over the candidates ----
    if (tid == 0) {
        float lv[TOPK]; int li[TOPK];
#pragma unroll
        for (int k = 0; k < TOPK; k++) { lv[k] = -INFINITY; li[k] = 0x7fffffff; }
        const int c = s_cnt;
        if (c <= CAP) {
            for (int i = 0; i < c; i++) ins8(s_cv[i], s_ci[i], lv, li);
        } else {
            // exact overflow fallback: serial rescan in index order
            for (int i = 0; i < navail; i++) {
                float v = __ldg(lm + base + i);
                if (v >= t) ins8(v, start + i, lv, li);
            }
        }
        float* ov = g_cv + (pos * SPLIT + seg) * TOPK;
        int*   oi = g_ci + (pos * SPLIT + seg) * TOPK;
#pragma unroll
        for (int k = 0; k < TOPK; k++) { ov[k] = lv[k]; oi[k] = li[k]; }
    }
}

// ---------------- kernel 2: merge segments + score + argmax (heavy positions only) ----------------
__global__ __launch_bounds__(NT2)
void dvat_final_kernel(const float* __restrict__ dgrad,
                       const float* __restrict__ semb,
                       const float* __restrict__ emb,
                       const int*   __restrict__ tok,
                       const int*   __restrict__ amask,
                       float*       __restrict__ out)
{
    const int widx = blockIdx.x;
    const int cnt  = g_cnt;
    if (widx >= cnt) return;
    const int pos  = g_wl[widx];
    const int tid  = threadIdx.x;
    const int st   = tok[pos];

    __shared__ __align__(16) float s_dg[DDIM];
    __shared__ __align__(16) float s_sr[DDIM];
    __shared__ float s_cv[SPLIT * TOPK];
    __shared__ int   s_ci[SPLIT * TOPK];
    __shared__ float t8v[TOPK];
    __shared__ int   t8i[TOPK];
    __shared__ float cscore[TOPK];
    __shared__ int   cidx[TOPK];

    {
        const float4* g4 = (const float4*)(dgrad + (size_t)pos * DDIM);
        const float4* s4 = (const float4*)(semb  + (size_t)pos * DDIM);
        float4* sg = (float4*)s_dg;
        float4* ss = (float4*)s_sr;
        for (int j = tid; j < DDIM / 4; j += NT2) { sg[j] = g4[j]; ss[j] = s4[j]; }
    }
    if (tid < SPLIT * TOPK) {
        s_cv[tid] = g_cv[pos * SPLIT * TOPK + tid];
        s_ci[tid] = g_ci[pos * SPLIT * TOPK + tid];
    }
    __syncthreads();

    // single-thread 16-way merge of sorted lists -> global top-8 (exact jax order)
    if (tid == 0) {
        int head[SPLIT];
#pragma unroll
        for (int s = 0; s < SPLIT; s++) head[s] = 0;
#pragma unroll
        for (int k = 0; k < TOPK; k++) {
            float bv = -INFINITY; int bi = 0x7fffffff; int bs = 0;
#pragma unroll
            for (int s = 0; s < SPLIT; s++) {
                int h = head[s];
                float v = s_cv[s * TOPK + h];
                int   i = s_ci[s * TOPK + h];
                if (better(v, i, bv, bi)) { bv = v; bi = i; bs = s; }
            }
            t8v[k] = bv; t8i[k] = bi;
            head[bs] = min(head[bs] + 1, TOPK - 1);
        }
    }
    __syncthreads();

    // one warp per candidate scoring
    const int am   = amask[pos];
    const int wid  = tid >> 5;
    const int lane = tid & 31;

    int v = t8i[wid] * am;
    float score = -INFINITY;
    if (v >= NSPECIAL && v != st) {
        const float4* ev = (const float4*)(emb + (size_t)v * DDIM);
        const float4* g4 = (const float4*)s_dg;
        const float4* s4 = (const float4*)s_sr;
        float gdot = 0.f, sdot = 0.f, vsq = 0.f, pdot = 0.f, ssq = 0.f;
#pragma unroll
        for (int j = lane; j < DDIM / 4; j += 32) {
            float4 e = __ldg(ev + j);
            float4 g = g4[j];
            float4 s = s4[j];
            gdot += e.x * g.x + e.y * g.y + e.z * g.z + e.w * g.w;
            sdot += e.x * s.x + e.y * s.y + e.z * s.z + e.w * s.w;
            vsq  += e.x * e.x + e.y * e.y + e.z * e.z + e.w * e.w;
            pdot += g.x * s.x + g.y * s.y + g.z * s.z + g.w * s.w;
            ssq  += s.x * s.x + s.y * s.y + s.z * s.z + s.w * s.w;
        }
#pragma unroll
        for (int o = 16; o > 0; o >>= 1) {
            gdot += __shfl_down_sync(0xffffffffu, gdot, o);
            sdot += __shfl_down_sync(0xffffffffu, sdot, o);
            vsq  += __shfl_down_sync(0xffffffffu, vsq,  o);
            pdot += __shfl_down_sync(0xffffffffu, pdot, o);
            ssq  += __shfl_down_sync(0xffffffffu, ssq,  o);
        }
        if (lane == 0) {
            float sqn = ssq + vsq - 2.0f * sdot;
            float dn  = sqrtf(fmaxf(sqn, 0.0f) + 1e-20f);
            score = (gdot - pdot) / dn;
        }
    }
    if (lane == 0) { cscore[wid] = score; cidx[wid] = v; }
    __syncthreads();

    if (tid == 0) {
        float best = 0.f; int bi = 0; bool found = false;
#pragma unroll
        for (int k = 0; k < TOPK; k++) {
            float sc = cscore[k]; int vi = cidx[k];
            if (sc != -INFINITY) {
                if (!found || sc > best || (sc == best && vi < bi)) {
                    best = sc; bi = vi; found = true;
                }
            }
        }
        out[pos] = (float)(found ? bi : 0);
    }
}

extern "C" void kernel_launch(void* const* d_in, const int* in_sizes, int n_in,
                              void* d_out, int out_size) {
    // size-pattern-driven input identification (order-robust)
    int idx_lm = 0, idx_emb = 0;
    long sz_lm = -1, sz_emb = -1;
    for (int i = 0; i < n_in; i++) {
        long s = in_sizes[i];
        if (s > sz_lm) { sz_emb = sz_lm; idx_emb = idx_lm; sz_lm = s; idx_lm = i; }
        else if (s > sz_emb) { sz_emb = s; idx_emb = i; }
    }
    int mids[2], nm = 0, smalls[3], ns = 0;
    long sz_small = 0x7fffffff;
    for (int i = 0; i < n_in; i++)
        if (i != idx_lm && i != idx_emb && (long)in_sizes[i] < sz_small) sz_small = in_sizes[i];
    for (int i = 0; i < n_in; i++) {
        if (i == idx_lm || i == idx_emb) continue;
        if ((long)in_sizes[i] == sz_small) { if (ns < 3) smalls[ns++] = i; }
        else                               { if (nm < 2) mids[nm++] = i; }
    }
    int idx_dg = mids[0], idx_se = mids[1];
    int idx_tok, idx_am, idx_ru;
    if (smalls[0] == 0) { idx_am = smalls[0]; idx_ru = smalls[1]; idx_tok = smalls[2]; }
    else                { idx_tok = smalls[0]; idx_am = smalls[1]; idx_ru = smalls[2]; }

    const float* dgrad = (const float*)d_in[idx_dg];
    const float* semb  = (const float*)d_in[idx_se];
    const float* emb   = (const float*)d_in[idx_emb];
    const int*   tok   = (const int*)  d_in[idx_tok];
    const float* lm    = (const float*)d_in[idx_lm];
    const int*   am    = (const int*)  d_in[idx_am];
    const float* ru    = (const float*)d_in[idx_ru];
    float* out = (float*)d_out;

    const int BS = in_sizes[idx_tok];                   // B*S = 2048
    const int V  = (int)((long)in_sizes[idx_lm] / BS);  // 30522
    int seg_len = ((V + SPLIT - 1) / SPLIT + 1) & ~1;   // even; 1908 for V=30522

    swap_compact_kernel<<<1, NT0>>>(tok, ru, out, BS);
    dim3 g1(BS, SPLIT);
    topk_seg_kernel<<<g1, NT1>>>(lm, V, seg_len);
    dvat_final_kernel<<<BS, NT2>>>(dgrad, semb, emb, tok, am, out);
}